// round 1
// baseline (speedup 1.0000x reference)
#include <cuda_runtime.h>

#define NTHREADS 128

// inverse of the low-5-bit source-permutation pi0 (see derivation in analysis)
__device__ constexpr int pi0inv(int m) {
    int m0 = m & 1, m1 = (m >> 1) & 1, m2 = (m >> 2) & 1, m3 = (m >> 3) & 1, m4 = (m >> 4) & 1;
    int r0 = m0 ^ m1;
    int r1 = m1 ^ m2 ^ m3;
    int r2 = m2 ^ m3;
    int r3 = m3 ^ m4;
    int r4 = m4;
    return r0 | (r1 << 1) | (r2 << 2) | (r3 << 3) | (r4 << 4);
}

// RY butterfly over register-index bit K: new0 = c*x0 - s*x1 ; new1 = s*x0 + c*x1
template <int K>
__device__ __forceinline__ void ry_stage(float* a, float c, float s) {
#pragma unroll
    for (int r = 0; r < 32; ++r) {
        if ((r & (1 << K)) == 0) {
            float x0 = a[r];
            float x1 = a[r | (1 << K)];
            a[r]            = fmaf(c, x0, -(s * x1));
            a[r | (1 << K)] = fmaf(s, x0, c * x1);
        }
    }
}

__global__ void __launch_bounds__(NTHREADS)
qsim_kernel(const float* __restrict__ feats,
            const float* __restrict__ qp,
            float* __restrict__ out)
{
    // state, stored XOR-swizzled: phys_elem = idx ^ (((idx>>5)&7)<<2)
    __shared__ float4 st4[1024];
    float* stf = reinterpret_cast<float*>(st4);
    __shared__ float csc[240], css[240];
    __shared__ float warp_ssq[4];
    __shared__ float rsum[48];
    __shared__ float inv_total;

    const int t = threadIdx.x;
    const int b = blockIdx.x;

    // ---- per-layer RY coefficients: theta = qp[(L+1)*12 + j], c=cos(th/2), s=sin(th/2)
    for (int i = t; i < 240; i += NTHREADS) {
        float th = 0.5f * qp[12 + i];
        csc[i] = cosf(th);
        css[i] = sinf(th);
    }

    // ---- embed: tanh(x)*pi/2 for 2048 feats, 0.5 padding for the rest (unnormalized;
    //      the 1/||s||^2 factor is applied to the final expvals since everything is linear)
    const float4* frow = reinterpret_cast<const float4*>(feats + (size_t)b * 2048);
    const float PIO2 = 1.5707963267948966f;
    float acc = 4.0f;  // this thread's share of the padding sum-sq: 16 * 0.25
#pragma unroll
    for (int v = 0; v < 4; ++v) {
        int f4i = v * 128 + t;
        float4 x = frow[f4i];
        float4 y;
        y.x = tanhf(x.x) * PIO2;
        y.y = tanhf(x.y) * PIO2;
        y.z = tanhf(x.z) * PIO2;
        y.w = tanhf(x.w) * PIO2;
        acc += y.x * y.x + y.y * y.y + y.z * y.z + y.w * y.w;
        st4[f4i ^ ((f4i >> 3) & 7)] = y;
    }
#pragma unroll
    for (int v = 0; v < 4; ++v) {
        int f4i = 512 + v * 128 + t;
        st4[f4i ^ ((f4i >> 3) & 7)] = make_float4(0.5f, 0.5f, 0.5f, 0.5f);
    }

    // block reduce sum of squares
#pragma unroll
    for (int o = 16; o; o >>= 1) acc += __shfl_xor_sync(0xffffffffu, acc, o);
    if ((t & 31) == 0) warp_ssq[t >> 5] = acc;
    __syncthreads();
    if (t == 0)
        inv_total = 1.0f / (warp_ssq[0] + warp_ssq[1] + warp_ssq[2] + warp_ssq[3]);

    // ---- pass-A thread constants: source thread-block sigma(t) for the entangling gather
    int t0 = t & 1, t1 = (t >> 1) & 1, t2 = (t >> 2) & 1, t3 = (t >> 3) & 1;
    int t4 = (t >> 4) & 1, t5 = (t >> 5) & 1, t6 = (t >> 6) & 1;
    int hi = (t0 ^ t1)
           | ((t1 ^ t2 ^ t3) << 1)
           | ((t2 ^ t3) << 2)
           | ((t3 ^ t4 ^ t5) << 3)
           | ((t4 ^ t5) << 4)
           | ((t5 ^ t6) << 5)
           | (t6 << 6);
    int e   = t0 ^ t1;               // parity feeding src bit 4
    int xA  = (e << 2) ^ (hi & 7);   // float4-granularity XOR: load perm + bank swizzle
    int hi8 = hi * 8;
    int baseB = ((t >> 5) << 10) | (t & 31);
    int xC = (t >> 2) & 7;
    __syncthreads();

#pragma unroll 1
    for (int L = 0; L < 20; ++L) {
        const float* cc = &csc[L * 12];
        const float* ss = &css[L * 12];

        // ===== pass A: entangling gather + RY on qubits 11..7 (idx bits 0..4) =====
        float rg[32];
#pragma unroll
        for (int j = 0; j < 8; ++j) {
            float4 v = st4[hi8 + (j ^ xA)];
            rg[pi0inv(4 * j + 0)] = v.x;
            rg[pi0inv(4 * j + 1)] = v.y;
            rg[pi0inv(4 * j + 2)] = v.z;
            rg[pi0inv(4 * j + 3)] = v.w;
        }
        ry_stage<0>(rg, cc[11], ss[11]);
        ry_stage<1>(rg, cc[10], ss[10]);
        ry_stage<2>(rg, cc[9], ss[9]);
        ry_stage<3>(rg, cc[8], ss[8]);
        ry_stage<4>(rg, cc[7], ss[7]);
        __syncthreads();  // all gathers done before overwriting blocks
#pragma unroll
        for (int j = 0; j < 8; ++j)
            st4[t * 8 + (j ^ (t & 7))] =
                make_float4(rg[4 * j], rg[4 * j + 1], rg[4 * j + 2], rg[4 * j + 3]);
        __syncthreads();

        // ===== pass B: RY on qubits 6..2 (idx bits 5..9), in-place per-thread set =====
        float bm[32];
#pragma unroll
        for (int m = 0; m < 32; ++m)
            bm[m] = stf[baseB ^ ((m << 5) ^ ((m & 7) << 2))];
        ry_stage<0>(bm, cc[6], ss[6]);
        ry_stage<1>(bm, cc[5], ss[5]);
        ry_stage<2>(bm, cc[4], ss[4]);
        ry_stage<3>(bm, cc[3], ss[3]);
        ry_stage<4>(bm, cc[2], ss[2]);
#pragma unroll
        for (int m = 0; m < 32; ++m)
            stf[baseB ^ ((m << 5) ^ ((m & 7) << 2))] = bm[m];
        __syncthreads();

        // ===== pass C: RY on qubits 1,0 (idx bits 10,11), in-place per-thread set =====
        float cv[32];
#pragma unroll
        for (int g = 0; g < 4; ++g)
#pragma unroll
            for (int hb = 0; hb < 2; ++hb) {
                float4 v = st4[(((g << 8) | (t << 1) | hb)) ^ xC];
                int rb = g * 8 + hb * 4;
                cv[rb + 0] = v.x; cv[rb + 1] = v.y; cv[rb + 2] = v.z; cv[rb + 3] = v.w;
            }
        ry_stage<4>(cv, cc[0], ss[0]);  // r bit4 = idx bit11 = qubit 0
        ry_stage<3>(cv, cc[1], ss[1]);  // r bit3 = idx bit10 = qubit 1
#pragma unroll
        for (int g = 0; g < 4; ++g)
#pragma unroll
            for (int hb = 0; hb < 2; ++hb) {
                int rb = g * 8 + hb * 4;
                st4[(((g << 8) | (t << 1) | hb)) ^ xC] =
                    make_float4(cv[rb], cv[rb + 1], cv[rb + 2], cv[rb + 3]);
            }
        __syncthreads();
    }

    // ===== expvals: out[q] = inv * sum_i s_i^2 * (1 - 2*bit_{11-q}(i)) =====
    float S = 0.f;
    float T[5] = {0.f, 0.f, 0.f, 0.f, 0.f};
#pragma unroll
    for (int j = 0; j < 8; ++j) {
        float4 v = st4[t * 8 + (j ^ (t & 7))];
        float vv[4] = {v.x, v.y, v.z, v.w};
#pragma unroll
        for (int k = 0; k < 4; ++k) {
            int r = 4 * j + k;
            float pp = vv[k] * vv[k];
            S += pp;
            if (r & 1)  T[0] += pp;
            if (r & 2)  T[1] += pp;
            if (r & 4)  T[2] += pp;
            if (r & 8)  T[3] += pp;
            if (r & 16) T[4] += pp;
        }
    }
    float val[12];
#pragma unroll
    for (int q = 0; q <= 6; ++q)
        val[q] = ((t >> (6 - q)) & 1) ? -S : S;   // idx bit (11-q) lives in thread bits
#pragma unroll
    for (int q = 7; q < 12; ++q)
        val[q] = S - 2.0f * T[11 - q];            // idx bit (11-q) lives in register bits

#pragma unroll
    for (int q = 0; q < 12; ++q)
#pragma unroll
        for (int o = 16; o; o >>= 1)
            val[q] += __shfl_xor_sync(0xffffffffu, val[q], o);
    if ((t & 31) == 0) {
#pragma unroll
        for (int q = 0; q < 12; ++q) rsum[(t >> 5) * 12 + q] = val[q];
    }
    __syncthreads();
    if (t < 12) {
        out[(size_t)b * 12 + t] =
            (rsum[t] + rsum[12 + t] + rsum[24 + t] + rsum[36 + t]) * inv_total;
    }
}

extern "C" void kernel_launch(void* const* d_in, const int* in_sizes, int n_in,
                              void* d_out, int out_size) {
    const float* feats = (const float*)d_in[0];
    const float* qp    = (const float*)d_in[1];
    float* out         = (float*)d_out;
    qsim_kernel<<<4096, NTHREADS>>>(feats, qp, out);
}